// round 1
// baseline (speedup 1.0000x reference)
#include <cuda_runtime.h>

#define NUM_LINK 9
#define DOF 7

// Forward kinematics chain, one thread per robot configuration.
// T = Tbase; for each link i: T = T @ Toff[i]; if revolute: T = T @ R_axis(q).
// Joints live at links 1..7 with axes z,y,z,y,z,y,z (links 0 and 8 fixed).
__global__ __launch_bounds__(256)
void fk_kernel(const float* __restrict__ Tbase,
               const float* __restrict__ Toff,
               const float* __restrict__ Q,
               float* __restrict__ out,
               int B)
{
    __shared__ float sToff[NUM_LINK * 16];
    for (int i = threadIdx.x; i < NUM_LINK * 16; i += blockDim.x)
        sToff[i] = Toff[i];
    __syncthreads();

    int b = blockIdx.x * blockDim.x + threadIdx.x;
    if (b >= B) return;

    // Load Tbase[b] (row-major 4x4). Warp covers a contiguous 2KB region.
    float T[16];
    const float4* tb = reinterpret_cast<const float4*>(Tbase + (size_t)b * 16);
    #pragma unroll
    for (int r = 0; r < 4; r++) {
        float4 v = tb[r];
        T[r * 4 + 0] = v.x; T[r * 4 + 1] = v.y;
        T[r * 4 + 2] = v.z; T[r * 4 + 3] = v.w;
    }

    // Load joint angles (warp covers contiguous 896B region).
    float q[DOF];
    const float* qb = Q + (size_t)b * DOF;
    #pragma unroll
    for (int j = 0; j < DOF; j++) q[j] = __ldg(qb + j);

    float* outb = out + (size_t)b * (NUM_LINK * 16);

    #pragma unroll
    for (int i = 0; i < NUM_LINK; i++) {
        // T = T @ Toff[i]  (full 4x4 for generality)
        const float* O = sToff + i * 16;
        float Tn[16];
        #pragma unroll
        for (int r = 0; r < 4; r++) {
            float a0 = T[r * 4 + 0], a1 = T[r * 4 + 1];
            float a2 = T[r * 4 + 2], a3 = T[r * 4 + 3];
            #pragma unroll
            for (int c = 0; c < 4; c++) {
                Tn[r * 4 + c] = fmaf(a0, O[0 * 4 + c],
                                fmaf(a1, O[1 * 4 + c],
                                fmaf(a2, O[2 * 4 + c],
                                     a3 * O[3 * 4 + c])));
            }
        }
        #pragma unroll
        for (int k = 0; k < 16; k++) T[k] = Tn[k];

        // Revolute joint at links 1..7: multiply by rotation on the right.
        // Right-multiplying by Rz/Ry only mixes two COLUMNS of T.
        if (i >= 1 && i <= 7) {
            float s, c;
            __sincosf(q[i - 1], &s, &c);
            if (i & 1) {
                // axis z: col0' = c*col0 + s*col1 ; col1' = -s*col0 + c*col1
                #pragma unroll
                for (int r = 0; r < 4; r++) {
                    float x = T[r * 4 + 0], y = T[r * 4 + 1];
                    T[r * 4 + 0] = fmaf(c, x,  s * y);
                    T[r * 4 + 1] = fmaf(c, y, -s * x);
                }
            } else {
                // axis y: col0' = c*col0 - s*col2 ; col2' = s*col0 + c*col2
                #pragma unroll
                for (int r = 0; r < 4; r++) {
                    float x = T[r * 4 + 0], z = T[r * 4 + 2];
                    T[r * 4 + 0] = fmaf(c, x, -s * z);
                    T[r * 4 + 2] = fmaf(c, z,  s * x);
                }
            }
        }

        // Write link i pose: 64B contiguous, 4 x STG.128.
        float4* o = reinterpret_cast<float4*>(outb + i * 16);
        o[0] = make_float4(T[0],  T[1],  T[2],  T[3]);
        o[1] = make_float4(T[4],  T[5],  T[6],  T[7]);
        o[2] = make_float4(T[8],  T[9],  T[10], T[11]);
        o[3] = make_float4(T[12], T[13], T[14], T[15]);
    }
}

extern "C" void kernel_launch(void* const* d_in, const int* in_sizes, int n_in,
                              void* d_out, int out_size)
{
    int B = out_size / (NUM_LINK * 16);

    // Identify inputs robustly by element count:
    //   Tbase: B*16, Toff: NUM_LINK*16 = 144, Q: B*DOF
    const float* Tbase = nullptr;
    const float* Toff  = nullptr;
    const float* Q     = nullptr;
    for (int i = 0; i < n_in; i++) {
        if (in_sizes[i] == NUM_LINK * 16)      Toff  = (const float*)d_in[i];
        else if (in_sizes[i] == B * 16)        Tbase = (const float*)d_in[i];
        else if (in_sizes[i] == B * DOF)       Q     = (const float*)d_in[i];
    }
    // Fallback to declared order if sizes were ambiguous
    if (!Tbase) Tbase = (const float*)d_in[0];
    if (!Toff)  Toff  = (const float*)d_in[1];
    if (!Q)     Q     = (const float*)d_in[2];

    float* out = (float*)d_out;

    const int threads = 256;
    const int blocks  = (B + threads - 1) / threads;
    fk_kernel<<<blocks, threads>>>(Tbase, Toff, Q, out, B);
}

// round 2
// speedup vs baseline: 3.4690x; 3.4690x over previous
#include <cuda_runtime.h>

#define NUM_LINK 9
#define DOF 7

// Forward kinematics, 4 threads per robot — one 4x4-matrix ROW per thread.
// Row independence: for T' = T @ M, row r of T' depends only on row r of T.
// Joints at links 1..7, axes z,y,z,y,z,y,z (links 0 and 8 fixed).
__global__ __launch_bounds__(256)
void fk_kernel(const float* __restrict__ Tbase,
               const float* __restrict__ Toff,
               const float* __restrict__ Q,
               float* __restrict__ out,
               int B)
{
    __shared__ float4 sToff[NUM_LINK * 4];
    if (threadIdx.x < NUM_LINK * 4)
        sToff[threadIdx.x] = reinterpret_cast<const float4*>(Toff)[threadIdx.x];
    __syncthreads();

    int g   = blockIdx.x * blockDim.x + threadIdx.x;
    int b   = g >> 2;           // robot index
    int sub = g & 3;            // row index 0..3
    bool valid = (b < B);
    int bb = valid ? b : (B - 1);   // clamp so shfl participation is uniform

    // Load my row of Tbase: warp reads a contiguous 512B span (fully coalesced).
    float4 r = reinterpret_cast<const float4*>(Tbase)[(size_t)bb * 4 + sub];

    // sincos split across the 4 lanes of this robot: lane t -> joints t, t+4.
    const float* qb = Q + (size_t)bb * DOF;
    float s_lo, c_lo, s_hi = 0.f, c_hi = 1.f;
    __sincosf(qb[sub], &s_lo, &c_lo);
    if (sub < 3) __sincosf(qb[sub + 4], &s_hi, &c_hi);

    float sj[DOF], cj[DOF];
    #pragma unroll
    for (int j = 0; j < 4; j++) {
        sj[j] = __shfl_sync(0xFFFFFFFFu, s_lo, j, 4);
        cj[j] = __shfl_sync(0xFFFFFFFFu, c_lo, j, 4);
    }
    #pragma unroll
    for (int j = 4; j < DOF; j++) {
        sj[j] = __shfl_sync(0xFFFFFFFFu, s_hi, j - 4, 4);
        cj[j] = __shfl_sync(0xFFFFFFFFu, c_hi, j - 4, 4);
    }

    float* outb = out + (size_t)b * (NUM_LINK * 16) + sub * 4;

    #pragma unroll
    for (int i = 0; i < NUM_LINK; i++) {
        // r = r @ Toff[i]  (row-vector times 4x4; Toff rows broadcast from smem)
        float4 o0 = sToff[i * 4 + 0];
        float4 o1 = sToff[i * 4 + 1];
        float4 o2 = sToff[i * 4 + 2];
        float4 o3 = sToff[i * 4 + 3];
        float4 n;
        n.x = fmaf(r.x, o0.x, fmaf(r.y, o1.x, fmaf(r.z, o2.x, r.w * o3.x)));
        n.y = fmaf(r.x, o0.y, fmaf(r.y, o1.y, fmaf(r.z, o2.y, r.w * o3.y)));
        n.z = fmaf(r.x, o0.z, fmaf(r.y, o1.z, fmaf(r.z, o2.z, r.w * o3.z)));
        n.w = fmaf(r.x, o0.w, fmaf(r.y, o1.w, fmaf(r.z, o2.w, r.w * o3.w)));
        r = n;

        // Revolute joint (links 1..7): right-multiply rotation mixes two columns.
        if (i >= 1 && i <= 7) {
            int j = i - 1;
            float s = sj[j], c = cj[j];
            if (i & 1) {
                // axis z: x' = c*x + s*y ; y' = c*y - s*x
                float x = r.x, y = r.y;
                r.x = fmaf(c, x,  s * y);
                r.y = fmaf(c, y, -s * x);
            } else {
                // axis y: x' = c*x - s*z ; z' = c*z + s*x
                float x = r.x, z = r.z;
                r.x = fmaf(c, x, -s * z);
                r.z = fmaf(c, z,  s * x);
            }
        }

        // Store row sub of link i: lanes 4k..4k+3 form one contiguous 64B chunk.
        if (valid)
            *reinterpret_cast<float4*>(outb + i * 16) = r;
    }
}

extern "C" void kernel_launch(void* const* d_in, const int* in_sizes, int n_in,
                              void* d_out, int out_size)
{
    int B = out_size / (NUM_LINK * 16);

    const float* Tbase = nullptr;
    const float* Toff  = nullptr;
    const float* Q     = nullptr;
    for (int i = 0; i < n_in; i++) {
        if (in_sizes[i] == NUM_LINK * 16)      Toff  = (const float*)d_in[i];
        else if (in_sizes[i] == B * 16)        Tbase = (const float*)d_in[i];
        else if (in_sizes[i] == B * DOF)       Q     = (const float*)d_in[i];
    }
    if (!Tbase) Tbase = (const float*)d_in[0];
    if (!Toff)  Toff  = (const float*)d_in[1];
    if (!Q)     Q     = (const float*)d_in[2];

    float* out = (float*)d_out;

    const int threads = 256;
    long long total = (long long)B * 4;
    const int blocks = (int)((total + threads - 1) / threads);
    fk_kernel<<<blocks, threads>>>(Tbase, Toff, Q, out, B);
}